// round 6
// baseline (speedup 1.0000x reference)
#include <cuda_runtime.h>
#include <math.h>

#define T_TOK   8192
#define DM      1024
#define DFF     2048
#define N_EXP   8
#define SEG     8192   // worst-case tokens per expert segment
#define N_SEGS  9      // 8 routed + 1 shared ("expert 8")

// ---------------- scratch (device globals; no runtime allocation) -----------
__device__ int   g_count[N_EXP];
__device__ int   g_slot2tok[N_EXP * SEG];
__device__ int   g_tok_slot[T_TOK * 2];
__device__ float g_tok_w[T_TOK * 2];
__device__ float g_H[(size_t)N_SEGS * SEG * DFF];   // stage-1 activations
__device__ float g_EO[(size_t)N_SEGS * SEG * DM];   // stage-2 per-slot outputs

// ---------------- init ------------------------------------------------------
__global__ void init_counts_kernel() {
    if (threadIdx.x < N_EXP) g_count[threadIdx.x] = 0;
}

// ---------------- gate: 1 warp per token ------------------------------------
__global__ void gate_kernel(const float* __restrict__ x,
                            const float* __restrict__ gw) {
    int warp = (blockIdx.x * blockDim.x + threadIdx.x) >> 5;
    int lane = threadIdx.x & 31;
    if (warp >= T_TOK) return;

    const float4* xr = (const float4*)(x + (size_t)warp * DM);
    float acc[N_EXP];
#pragma unroll
    for (int e = 0; e < N_EXP; e++) acc[e] = 0.f;

    for (int i = lane; i < DM / 4; i += 32) {
        float4 xv = xr[i];
#pragma unroll
        for (int e = 0; e < N_EXP; e++) {
            float4 gv = ((const float4*)(gw + (size_t)e * DM))[i];
            acc[e] += xv.x * gv.x + xv.y * gv.y + xv.z * gv.z + xv.w * gv.w;
        }
    }
#pragma unroll
    for (int e = 0; e < N_EXP; e++) {
#pragma unroll
        for (int off = 16; off > 0; off >>= 1)
            acc[e] += __shfl_xor_sync(0xFFFFFFFFu, acc[e], off);
    }

    if (lane == 0) {
        // top-2 over logits (softmax is monotone); ties -> lowest index (jax top_k)
        int i0 = 0;
#pragma unroll
        for (int e = 1; e < N_EXP; e++) if (acc[e] > acc[i0]) i0 = e;
        int i1 = (i0 == 0) ? 1 : 0;
#pragma unroll
        for (int e = 0; e < N_EXP; e++)
            if (e != i0 && acc[e] > acc[i1]) i1 = e;

        // renormalized top-2 softmax weights: global denominator cancels
        float el = expf(acc[i1] - acc[i0]);
        float w0 = 1.f / (1.f + el);
        float w1 = el / (1.f + el);

        int p0 = atomicAdd(&g_count[i0], 1);
        int p1 = atomicAdd(&g_count[i1], 1);
        int s0 = i0 * SEG + p0;
        int s1 = i1 * SEG + p1;
        g_slot2tok[s0] = warp;
        g_slot2tok[s1] = warp;
        g_tok_slot[warp * 2]     = s0;
        g_tok_slot[warp * 2 + 1] = s1;
        g_tok_w[warp * 2]     = w0;
        g_tok_w[warp * 2 + 1] = w1;
    }
}

// ---------------- grouped NT GEMM (C = A * B^T), 128x128x16 SIMT ------------
// STAGE1: A = gathered x rows [*,DM], B = w1[e]/ws1 [DFF,DM], C = H, ReLU
// STAGE2: A = H rows          [*,DFF], B = w2[e]/ws2 [DM,DFF], C = EO
template <bool STAGE1>
__global__ __launch_bounds__(256, 2)
void gemm_kernel(const float* __restrict__ X,
                 const float* __restrict__ Wr,
                 const float* __restrict__ Ws,
                 const float* __restrict__ br,
                 const float* __restrict__ bs) {
    constexpr int BM = 128, BN = 128, BK = 16;
    constexpr int N = STAGE1 ? DFF : DM;
    constexpr int K = STAGE1 ? DM  : DFF;

    const int e   = blockIdx.z;
    const int cnt = (e < N_EXP) ? g_count[e] : T_TOK;
    const int m0  = blockIdx.x * BM;
    if (m0 >= cnt) return;
    const int n0 = blockIdx.y * BN;

    const float* Bw   = (e < N_EXP) ? Wr + (size_t)e * N * K : Ws;
    const float* bias = (e < N_EXP) ? br + (size_t)e * N     : bs;

    __shared__ float As[BK][BM];
    __shared__ float Bs[BK][BN];
    __shared__ const float* Arow[BM];

    const int tid = threadIdx.x;
    if (tid < BM) {
        int m = m0 + tid;
        const float* p;
        if (STAGE1) {
            int tok;
            if (e < N_EXP) tok = (m < cnt) ? g_slot2tok[e * SEG + m] : 0;
            else           tok = m;  // shared expert: identity over all tokens
            p = X + (size_t)tok * K;
        } else {
            p = g_H + ((size_t)e * SEG + m) * K;
        }
        Arow[tid] = p;
    }
    __syncthreads();

    const int lRow = tid >> 2;         // 0..63
    const int lK   = (tid & 3) << 2;   // 0,4,8,12
    const int ty   = tid >> 4;         // 0..15
    const int tx   = tid & 15;         // 0..15

    float acc[8][8];
#pragma unroll
    for (int i = 0; i < 8; i++)
#pragma unroll
        for (int j = 0; j < 8; j++) acc[i][j] = 0.f;

    for (int k0 = 0; k0 < K; k0 += BK) {
#pragma unroll
        for (int p = 0; p < 2; p++) {
            int m = lRow + p * 64;
            float4 va = *(const float4*)(Arow[m] + k0 + lK);
            As[lK + 0][m] = va.x; As[lK + 1][m] = va.y;
            As[lK + 2][m] = va.z; As[lK + 3][m] = va.w;

            int n = lRow + p * 64;
            float4 vb = *(const float4*)(Bw + (size_t)(n0 + n) * K + k0 + lK);
            Bs[lK + 0][n] = vb.x; Bs[lK + 1][n] = vb.y;
            Bs[lK + 2][n] = vb.z; Bs[lK + 3][n] = vb.w;
        }
        __syncthreads();

#pragma unroll
        for (int kk = 0; kk < BK; kk++) {
            float rM[8], rN[8];
            *(float4*)&rM[0] = *(const float4*)&As[kk][ty * 8];
            *(float4*)&rM[4] = *(const float4*)&As[kk][ty * 8 + 4];
            *(float4*)&rN[0] = *(const float4*)&Bs[kk][tx * 8];
            *(float4*)&rN[4] = *(const float4*)&Bs[kk][tx * 8 + 4];
#pragma unroll
            for (int i = 0; i < 8; i++)
#pragma unroll
                for (int j = 0; j < 8; j++)
                    acc[i][j] = fmaf(rM[i], rN[j], acc[i][j]);
        }
        __syncthreads();
    }

    float* Cbase = STAGE1 ? g_H : g_EO;
#pragma unroll
    for (int i = 0; i < 8; i++) {
        int m = m0 + ty * 8 + i;
        if (m >= cnt) continue;
        float* crow = Cbase + ((size_t)e * SEG + m) * N + n0;
#pragma unroll
        for (int j = 0; j < 8; j += 4) {
            int n = tx * 8 + j;
            float4 bv = *(const float4*)(bias + n0 + n);
            float4 o;
            o.x = acc[i][j + 0] + bv.x;
            o.y = acc[i][j + 1] + bv.y;
            o.z = acc[i][j + 2] + bv.z;
            o.w = acc[i][j + 3] + bv.w;
            if (STAGE1) {
                o.x = fmaxf(o.x, 0.f); o.y = fmaxf(o.y, 0.f);
                o.z = fmaxf(o.z, 0.f); o.w = fmaxf(o.w, 0.f);
            }
            *(float4*)(crow + n) = o;
        }
    }
}

// ---------------- combine: weighted routed outputs + shared -----------------
__global__ void combine_kernel(float* __restrict__ out) {
    int t = blockIdx.x;
    int i = threadIdx.x;  // 256 threads, D/4 float4s
    int s0 = g_tok_slot[t * 2];
    int s1 = g_tok_slot[t * 2 + 1];
    float w0 = g_tok_w[t * 2];
    float w1 = g_tok_w[t * 2 + 1];

    const float4* EO = (const float4*)g_EO;
    float4 a = EO[(size_t)s0 * (DM / 4) + i];
    float4 b = EO[(size_t)s1 * (DM / 4) + i];
    float4 c = EO[((size_t)N_EXP * SEG + t) * (DM / 4) + i];
    float4 o;
    o.x = w0 * a.x + w1 * b.x + c.x;
    o.y = w0 * a.y + w1 * b.y + c.y;
    o.z = w0 * a.z + w1 * b.z + c.z;
    o.w = w0 * a.w + w1 * b.w + c.w;
    ((float4*)out)[(size_t)t * (DM / 4) + i] = o;
}

// ---------------- launch -----------------------------------------------------
extern "C" void kernel_launch(void* const* d_in, const int* in_sizes, int n_in,
                              void* d_out, int out_size) {
    const float* x   = (const float*)d_in[0];
    const float* gw  = (const float*)d_in[1];
    const float* w1  = (const float*)d_in[2];
    const float* b1  = (const float*)d_in[3];
    const float* w2  = (const float*)d_in[4];
    const float* b2  = (const float*)d_in[5];
    const float* ws1 = (const float*)d_in[6];
    const float* bs1 = (const float*)d_in[7];
    const float* ws2 = (const float*)d_in[8];
    const float* bs2 = (const float*)d_in[9];
    float* out = (float*)d_out;

    init_counts_kernel<<<1, 32>>>();
    gate_kernel<<<T_TOK / 8, 256>>>(x, gw);
    gemm_kernel<true ><<<dim3(SEG / 128, DFF / 128, N_SEGS), 256>>>(x, w1, ws1, b1, bs1);
    gemm_kernel<false><<<dim3(SEG / 128, DM  / 128, N_SEGS), 256>>>(x, w2, ws2, b2, bs2);
    combine_kernel<<<T_TOK, 256>>>(out);
}

// round 9
// speedup vs baseline: 1.0224x; 1.0224x over previous
#include <cuda_runtime.h>
#include <math.h>

#define T_TOK   8192
#define DM      1024
#define DFF     2048
#define N_EXP   8
#define SEG     8192   // worst-case tokens per expert segment
#define N_SEGS  9      // 8 routed + 1 shared ("expert 8")

// ---------------- scratch (device globals; no runtime allocation) -----------
__device__ int   g_count[N_EXP];
__device__ int   g_slot2tok[N_EXP * SEG];
__device__ int   g_tok_slot[T_TOK * 2];
__device__ float g_tok_w[T_TOK * 2];
__device__ float g_H[(size_t)N_SEGS * SEG * DFF];   // stage-1 activations
__device__ float g_EO[(size_t)N_SEGS * SEG * DM];   // stage-2 per-slot outputs

// ---------------- packed f32x2 helpers --------------------------------------
__device__ __forceinline__ unsigned long long pack_dup(float a) {
    unsigned long long r;
    asm("mov.b64 %0, {%1, %1};" : "=l"(r) : "r"(__float_as_uint(a)));
    return r;
}
__device__ __forceinline__ void fma2(unsigned long long& d,
                                     unsigned long long a,
                                     unsigned long long b) {
    asm("fma.rn.f32x2 %0, %1, %2, %0;" : "+l"(d) : "l"(a), "l"(b));
}
__device__ __forceinline__ float2 unpack2(unsigned long long v) {
    float2 f;
    unsigned int lo, hi;
    asm("mov.b64 {%0, %1}, %2;" : "=r"(lo), "=r"(hi) : "l"(v));
    f.x = __uint_as_float(lo);
    f.y = __uint_as_float(hi);
    return f;
}

// ---------------- init ------------------------------------------------------
__global__ void init_counts_kernel() {
    if (threadIdx.x < N_EXP) g_count[threadIdx.x] = 0;
}

// ---------------- gate: 1 warp per token ------------------------------------
__global__ void gate_kernel(const float* __restrict__ x,
                            const float* __restrict__ gw) {
    int warp = (blockIdx.x * blockDim.x + threadIdx.x) >> 5;
    int lane = threadIdx.x & 31;
    if (warp >= T_TOK) return;

    const float4* xr = (const float4*)(x + (size_t)warp * DM);
    float acc[N_EXP];
#pragma unroll
    for (int e = 0; e < N_EXP; e++) acc[e] = 0.f;

    for (int i = lane; i < DM / 4; i += 32) {
        float4 xv = xr[i];
#pragma unroll
        for (int e = 0; e < N_EXP; e++) {
            float4 gv = ((const float4*)(gw + (size_t)e * DM))[i];
            acc[e] += xv.x * gv.x + xv.y * gv.y + xv.z * gv.z + xv.w * gv.w;
        }
    }
#pragma unroll
    for (int e = 0; e < N_EXP; e++) {
#pragma unroll
        for (int off = 16; off > 0; off >>= 1)
            acc[e] += __shfl_xor_sync(0xFFFFFFFFu, acc[e], off);
    }

    if (lane == 0) {
        // top-2 over logits (softmax is monotone); ties -> lowest index (jax top_k)
        int i0 = 0;
#pragma unroll
        for (int e = 1; e < N_EXP; e++) if (acc[e] > acc[i0]) i0 = e;
        int i1 = (i0 == 0) ? 1 : 0;
#pragma unroll
        for (int e = 0; e < N_EXP; e++)
            if (e != i0 && acc[e] > acc[i1]) i1 = e;

        // renormalized top-2 softmax weights: global denominator cancels
        float el = expf(acc[i1] - acc[i0]);
        float w0 = 1.f / (1.f + el);
        float w1 = el / (1.f + el);

        int p0 = atomicAdd(&g_count[i0], 1);
        int p1 = atomicAdd(&g_count[i1], 1);
        int s0 = i0 * SEG + p0;
        int s1 = i1 * SEG + p1;
        g_slot2tok[s0] = warp;
        g_slot2tok[s1] = warp;
        g_tok_slot[warp * 2]     = s0;
        g_tok_slot[warp * 2 + 1] = s1;
        g_tok_w[warp * 2]     = w0;
        g_tok_w[warp * 2 + 1] = w1;
    }
}

// ---------------- grouped NT GEMM (C = A * B^T), 128x128x16, f32x2 FMA ------
// STAGE1: A = gathered x rows [*,DM], B = w1[e]/ws1 [DFF,DM], C = H, ReLU
// STAGE2: A = H rows          [*,DFF], B = w2[e]/ws2 [DM,DFF], C = EO
template <bool STAGE1>
__global__ __launch_bounds__(256, 2)
void gemm_kernel(const float* __restrict__ X,
                 const float* __restrict__ Wr,
                 const float* __restrict__ Ws,
                 const float* __restrict__ br,
                 const float* __restrict__ bs) {
    constexpr int BM = 128, BN = 128, BK = 16;
    constexpr int N = STAGE1 ? DFF : DM;
    constexpr int K = STAGE1 ? DM  : DFF;

    const int e   = blockIdx.z;
    const int cnt = (e < N_EXP) ? g_count[e] : T_TOK;
    const int m0  = blockIdx.x * BM;
    if (m0 >= cnt) return;
    const int n0 = blockIdx.y * BN;

    const float* Bw   = (e < N_EXP) ? Wr + (size_t)e * N * K : Ws;
    const float* bias = (e < N_EXP) ? br + (size_t)e * N     : bs;

    __shared__ float As[BK][BM];
    __shared__ float Bs[BK][BN];
    __shared__ const float* Arow[BM];

    const int tid = threadIdx.x;
    if (tid < BM) {
        int m = m0 + tid;
        const float* p;
        if (STAGE1) {
            int tok;
            if (e < N_EXP) tok = (m < cnt) ? g_slot2tok[e * SEG + m] : 0;
            else           tok = m;  // shared expert: identity over all tokens
            p = X + (size_t)tok * K;
        } else {
            p = g_H + ((size_t)e * SEG + m) * K;
        }
        Arow[tid] = p;
    }
    __syncthreads();

    const int lRow = tid >> 2;         // 0..63
    const int lK   = (tid & 3) << 2;   // 0,4,8,12
    const int ty   = tid >> 4;         // 0..15
    const int tx   = tid & 15;         // 0..15

    // 8x8 fp32 microtile held as 8x4 packed f32x2 lanes
    unsigned long long acc[8][4];
#pragma unroll
    for (int i = 0; i < 8; i++)
#pragma unroll
        for (int j = 0; j < 4; j++) acc[i][j] = 0ull;

    for (int k0 = 0; k0 < K; k0 += BK) {
#pragma unroll
        for (int p = 0; p < 2; p++) {
            int m = lRow + p * 64;
            float4 va = *(const float4*)(Arow[m] + k0 + lK);
            As[lK + 0][m] = va.x; As[lK + 1][m] = va.y;
            As[lK + 2][m] = va.z; As[lK + 3][m] = va.w;

            int n = lRow + p * 64;
            float4 vb = *(const float4*)(Bw + (size_t)(n0 + n) * K + k0 + lK);
            Bs[lK + 0][n] = vb.x; Bs[lK + 1][n] = vb.y;
            Bs[lK + 2][n] = vb.z; Bs[lK + 3][n] = vb.w;
        }
        __syncthreads();

#pragma unroll
        for (int kk = 0; kk < BK; kk++) {
            float rM[8];
            *(float4*)&rM[0] = *(const float4*)&As[kk][ty * 8];
            *(float4*)&rM[4] = *(const float4*)&As[kk][ty * 8 + 4];
            // B pairs are consecutive floats in shared -> load directly as 64-bit lanes
            unsigned long long rN[4];
            *(ulonglong2*)&rN[0] = *(const ulonglong2*)&Bs[kk][tx * 8];
            *(ulonglong2*)&rN[2] = *(const ulonglong2*)&Bs[kk][tx * 8 + 4];
#pragma unroll
            for (int i = 0; i < 8; i++) {
                unsigned long long md = pack_dup(rM[i]);
#pragma unroll
                for (int j = 0; j < 4; j++)
                    fma2(acc[i][j], md, rN[j]);
            }
        }
        __syncthreads();
    }

    float* Cbase = STAGE1 ? g_H : g_EO;
#pragma unroll
    for (int i = 0; i < 8; i++) {
        int m = m0 + ty * 8 + i;
        if (m >= cnt) continue;
        float* crow = Cbase + ((size_t)e * SEG + m) * N + n0;
#pragma unroll
        for (int jj = 0; jj < 2; jj++) {
            int n = tx * 8 + jj * 4;
            float4 bv = *(const float4*)(bias + n0 + n);
            float2 p0 = unpack2(acc[i][jj * 2 + 0]);
            float2 p1 = unpack2(acc[i][jj * 2 + 1]);
            float4 o;
            o.x = p0.x + bv.x;
            o.y = p0.y + bv.y;
            o.z = p1.x + bv.z;
            o.w = p1.y + bv.w;
            if (STAGE1) {
                o.x = fmaxf(o.x, 0.f); o.y = fmaxf(o.y, 0.f);
                o.z = fmaxf(o.z, 0.f); o.w = fmaxf(o.w, 0.f);
            }
            *(float4*)(crow + n) = o;
        }
    }
}

// ---------------- combine: weighted routed outputs + shared -----------------
__global__ void combine_kernel(float* __restrict__ out) {
    int t = blockIdx.x;
    int i = threadIdx.x;  // 256 threads, D/4 float4s
    int s0 = g_tok_slot[t * 2];
    int s1 = g_tok_slot[t * 2 + 1];
    float w0 = g_tok_w[t * 2];
    float w1 = g_tok_w[t * 2 + 1];

    const float4* EO = (const float4*)g_EO;
    float4 a = EO[(size_t)s0 * (DM / 4) + i];
    float4 b = EO[(size_t)s1 * (DM / 4) + i];
    float4 c = EO[((size_t)N_EXP * SEG + t) * (DM / 4) + i];
    float4 o;
    o.x = w0 * a.x + w1 * b.x + c.x;
    o.y = w0 * a.y + w1 * b.y + c.y;
    o.z = w0 * a.z + w1 * b.z + c.z;
    o.w = w0 * a.w + w1 * b.w + c.w;
    ((float4*)out)[(size_t)t * (DM / 4) + i] = o;
}

// ---------------- launch -----------------------------------------------------
extern "C" void kernel_launch(void* const* d_in, const int* in_sizes, int n_in,
                              void* d_out, int out_size) {
    const float* x   = (const float*)d_in[0];
    const float* gw  = (const float*)d_in[1];
    const float* w1  = (const float*)d_in[2];
    const float* b1  = (const float*)d_in[3];
    const float* w2  = (const float*)d_in[4];
    const float* b2  = (const float*)d_in[5];
    const float* ws1 = (const float*)d_in[6];
    const float* bs1 = (const float*)d_in[7];
    const float* ws2 = (const float*)d_in[8];
    const float* bs2 = (const float*)d_in[9];
    float* out = (float*)d_out;

    init_counts_kernel<<<1, 32>>>();
    gate_kernel<<<T_TOK / 8, 256>>>(x, gw);
    gemm_kernel<true ><<<dim3(SEG / 128, DFF / 128, N_SEGS), 256>>>(x, w1, ws1, b1, bs1);
    gemm_kernel<false><<<dim3(SEG / 128, DM  / 128, N_SEGS), 256>>>(x, w2, ws2, b2, bs2);
    combine_kernel<<<T_TOK, 256>>>(out);
}

// round 10
// speedup vs baseline: 1.0962x; 1.0722x over previous
#include <cuda_runtime.h>
#include <math.h>

#define T_TOK   8192
#define DM      1024
#define DFF     2048
#define N_EXP   8
#define SEG     8192   // worst-case tokens per expert segment
#define N_SEGS  9      // 8 routed + 1 shared ("expert 8")

// ---------------- scratch (device globals; no runtime allocation) -----------
__device__ int   g_count[N_EXP];
__device__ int   g_slot2tok[N_EXP * SEG];
__device__ int   g_tok_slot[T_TOK * 2];
__device__ float g_tok_w[T_TOK * 2];
__device__ float g_H[(size_t)N_SEGS * SEG * DFF];   // stage-1 activations
__device__ float g_EO[(size_t)N_SEGS * SEG * DM];   // stage-2 per-slot outputs

// ---------------- packed f32x2 helpers --------------------------------------
__device__ __forceinline__ unsigned long long pack_dup(float a) {
    unsigned long long r;
    asm("mov.b64 %0, {%1, %1};" : "=l"(r) : "r"(__float_as_uint(a)));
    return r;
}
__device__ __forceinline__ void fma2(unsigned long long& d,
                                     unsigned long long a,
                                     unsigned long long b) {
    asm("fma.rn.f32x2 %0, %1, %2, %0;" : "+l"(d) : "l"(a), "l"(b));
}
__device__ __forceinline__ float2 unpack2(unsigned long long v) {
    float2 f;
    unsigned int lo, hi;
    asm("mov.b64 {%0, %1}, %2;" : "=r"(lo), "=r"(hi) : "l"(v));
    f.x = __uint_as_float(lo);
    f.y = __uint_as_float(hi);
    return f;
}

// ---------------- init ------------------------------------------------------
__global__ void init_counts_kernel() {
    if (threadIdx.x < N_EXP) g_count[threadIdx.x] = 0;
}

// ---------------- gate: 1 warp per token ------------------------------------
__global__ void gate_kernel(const float* __restrict__ x,
                            const float* __restrict__ gw) {
    int warp = (blockIdx.x * blockDim.x + threadIdx.x) >> 5;
    int lane = threadIdx.x & 31;
    if (warp >= T_TOK) return;

    const float4* xr = (const float4*)(x + (size_t)warp * DM);
    float acc[N_EXP];
#pragma unroll
    for (int e = 0; e < N_EXP; e++) acc[e] = 0.f;

    for (int i = lane; i < DM / 4; i += 32) {
        float4 xv = xr[i];
#pragma unroll
        for (int e = 0; e < N_EXP; e++) {
            float4 gv = ((const float4*)(gw + (size_t)e * DM))[i];
            acc[e] += xv.x * gv.x + xv.y * gv.y + xv.z * gv.z + xv.w * gv.w;
        }
    }
#pragma unroll
    for (int e = 0; e < N_EXP; e++) {
#pragma unroll
        for (int off = 16; off > 0; off >>= 1)
            acc[e] += __shfl_xor_sync(0xFFFFFFFFu, acc[e], off);
    }

    if (lane == 0) {
        // top-2 over logits (softmax is monotone); ties -> lowest index (jax top_k)
        int i0 = 0;
#pragma unroll
        for (int e = 1; e < N_EXP; e++) if (acc[e] > acc[i0]) i0 = e;
        int i1 = (i0 == 0) ? 1 : 0;
#pragma unroll
        for (int e = 0; e < N_EXP; e++)
            if (e != i0 && acc[e] > acc[i1]) i1 = e;

        // renormalized top-2 softmax weights: global denominator cancels
        float el = expf(acc[i1] - acc[i0]);
        float w0 = 1.f / (1.f + el);
        float w1 = el / (1.f + el);

        int p0 = atomicAdd(&g_count[i0], 1);
        int p1 = atomicAdd(&g_count[i1], 1);
        int s0 = i0 * SEG + p0;
        int s1 = i1 * SEG + p1;
        g_slot2tok[s0] = warp;
        g_slot2tok[s1] = warp;
        g_tok_slot[warp * 2]     = s0;
        g_tok_slot[warp * 2 + 1] = s1;
        g_tok_w[warp * 2]     = w0;
        g_tok_w[warp * 2 + 1] = w1;
    }
}

// ---------------- grouped NT GEMM (C = A * B^T), 128x128x16, f32x2 FMA ------
// Software-pipelined: register prefetch of next k-tile + double-buffered smem.
// STAGE1: A = gathered x rows [*,DM], B = w1[e]/ws1 [DFF,DM], C = H, ReLU
// STAGE2: A = H rows          [*,DFF], B = w2[e]/ws2 [DM,DFF], C = EO
template <bool STAGE1>
__global__ __launch_bounds__(256, 2)
void gemm_kernel(const float* __restrict__ X,
                 const float* __restrict__ Wr,
                 const float* __restrict__ Ws,
                 const float* __restrict__ br,
                 const float* __restrict__ bs) {
    constexpr int BM = 128, BN = 128, BK = 16;
    constexpr int N = STAGE1 ? DFF : DM;
    constexpr int K = STAGE1 ? DM  : DFF;

    const int e   = blockIdx.z;
    const int cnt = (e < N_EXP) ? g_count[e] : T_TOK;
    const int m0  = blockIdx.x * BM;
    if (m0 >= cnt) return;
    const int n0 = blockIdx.y * BN;

    const float* Bw   = (e < N_EXP) ? Wr + (size_t)e * N * K : Ws;
    const float* bias = (e < N_EXP) ? br + (size_t)e * N     : bs;

    __shared__ float As[2][BK][BM];
    __shared__ float Bs[2][BK][BN];

    const int tid  = threadIdx.x;
    const int lRow = tid >> 2;         // 0..63
    const int lK   = (tid & 3) << 2;   // 0,4,8,12
    const int ty   = tid >> 4;         // 0..15
    const int tx   = tid & 15;         // 0..15

    // per-thread A row pointers (2: rows lRow and lRow+64)
    const float* aP[2];
#pragma unroll
    for (int p = 0; p < 2; p++) {
        int m = m0 + lRow + p * 64;
        if (STAGE1) {
            int tok;
            if (e < N_EXP) tok = (m < cnt) ? g_slot2tok[e * SEG + m] : 0;
            else           tok = m;  // shared expert: identity over all tokens
            aP[p] = X + (size_t)tok * K;
        } else {
            aP[p] = g_H + ((size_t)e * SEG + m) * K;
        }
    }
    const float* bP[2] = { Bw + (size_t)(n0 + lRow) * K,
                           Bw + (size_t)(n0 + lRow + 64) * K };

    // 8x8 fp32 microtile held as 8x4 packed f32x2 lanes
    unsigned long long acc[8][4];
#pragma unroll
    for (int i = 0; i < 8; i++)
#pragma unroll
        for (int j = 0; j < 4; j++) acc[i][j] = 0ull;

    float4 pva[2], pvb[2];

    // prologue: tile 0
#pragma unroll
    for (int p = 0; p < 2; p++) {
        pva[p] = *(const float4*)(aP[p] + lK);
        pvb[p] = *(const float4*)(bP[p] + lK);
    }
#pragma unroll
    for (int p = 0; p < 2; p++) {
        int m = lRow + p * 64;
        As[0][lK + 0][m] = pva[p].x; As[0][lK + 1][m] = pva[p].y;
        As[0][lK + 2][m] = pva[p].z; As[0][lK + 3][m] = pva[p].w;
        Bs[0][lK + 0][m] = pvb[p].x; Bs[0][lK + 1][m] = pvb[p].y;
        Bs[0][lK + 2][m] = pvb[p].z; Bs[0][lK + 3][m] = pvb[p].w;
    }
    __syncthreads();

    constexpr int NT = K / BK;
    for (int t = 0; t < NT; t++) {
        // issue next tile's global loads before compute (latency hiding)
        if (t + 1 < NT) {
            int k0 = (t + 1) * BK;
#pragma unroll
            for (int p = 0; p < 2; p++) {
                pva[p] = *(const float4*)(aP[p] + k0 + lK);
                pvb[p] = *(const float4*)(bP[p] + k0 + lK);
            }
        }

        const int cur = t & 1;
#pragma unroll
        for (int kk = 0; kk < BK; kk++) {
            float rM[8];
            *(float4*)&rM[0] = *(const float4*)&As[cur][kk][ty * 8];
            *(float4*)&rM[4] = *(const float4*)&As[cur][kk][ty * 8 + 4];
            unsigned long long rN[4];
            *(ulonglong2*)&rN[0] = *(const ulonglong2*)&Bs[cur][kk][tx * 8];
            *(ulonglong2*)&rN[2] = *(const ulonglong2*)&Bs[cur][kk][tx * 8 + 4];
#pragma unroll
            for (int i = 0; i < 8; i++) {
                unsigned long long md = pack_dup(rM[i]);
#pragma unroll
                for (int j = 0; j < 4; j++)
                    fma2(acc[i][j], md, rN[j]);
            }
        }

        if (t + 1 < NT) {
            const int nxt = (t + 1) & 1;
#pragma unroll
            for (int p = 0; p < 2; p++) {
                int m = lRow + p * 64;
                As[nxt][lK + 0][m] = pva[p].x; As[nxt][lK + 1][m] = pva[p].y;
                As[nxt][lK + 2][m] = pva[p].z; As[nxt][lK + 3][m] = pva[p].w;
                Bs[nxt][lK + 0][m] = pvb[p].x; Bs[nxt][lK + 1][m] = pvb[p].y;
                Bs[nxt][lK + 2][m] = pvb[p].z; Bs[nxt][lK + 3][m] = pvb[p].w;
            }
            __syncthreads();
        }
    }

    float* Cbase = STAGE1 ? g_H : g_EO;
#pragma unroll
    for (int i = 0; i < 8; i++) {
        int m = m0 + ty * 8 + i;
        if (m >= cnt) continue;
        float* crow = Cbase + ((size_t)e * SEG + m) * N + n0;
#pragma unroll
        for (int jj = 0; jj < 2; jj++) {
            int n = tx * 8 + jj * 4;
            float4 bv = *(const float4*)(bias + n0 + n);
            float2 p0 = unpack2(acc[i][jj * 2 + 0]);
            float2 p1 = unpack2(acc[i][jj * 2 + 1]);
            float4 o;
            o.x = p0.x + bv.x;
            o.y = p0.y + bv.y;
            o.z = p1.x + bv.z;
            o.w = p1.y + bv.w;
            if (STAGE1) {
                o.x = fmaxf(o.x, 0.f); o.y = fmaxf(o.y, 0.f);
                o.z = fmaxf(o.z, 0.f); o.w = fmaxf(o.w, 0.f);
            }
            *(float4*)(crow + n) = o;
        }
    }
}

// ---------------- combine: weighted routed outputs + shared -----------------
__global__ void combine_kernel(float* __restrict__ out) {
    int t = blockIdx.x;
    int i = threadIdx.x;  // 256 threads, D/4 float4s
    int s0 = g_tok_slot[t * 2];
    int s1 = g_tok_slot[t * 2 + 1];
    float w0 = g_tok_w[t * 2];
    float w1 = g_tok_w[t * 2 + 1];

    const float4* EO = (const float4*)g_EO;
    float4 a = EO[(size_t)s0 * (DM / 4) + i];
    float4 b = EO[(size_t)s1 * (DM / 4) + i];
    float4 c = EO[((size_t)N_EXP * SEG + t) * (DM / 4) + i];
    float4 o;
    o.x = w0 * a.x + w1 * b.x + c.x;
    o.y = w0 * a.y + w1 * b.y + c.y;
    o.z = w0 * a.z + w1 * b.z + c.z;
    o.w = w0 * a.w + w1 * b.w + c.w;
    ((float4*)out)[(size_t)t * (DM / 4) + i] = o;
}

// ---------------- launch -----------------------------------------------------
extern "C" void kernel_launch(void* const* d_in, const int* in_sizes, int n_in,
                              void* d_out, int out_size) {
    const float* x   = (const float*)d_in[0];
    const float* gw  = (const float*)d_in[1];
    const float* w1  = (const float*)d_in[2];
    const float* b1  = (const float*)d_in[3];
    const float* w2  = (const float*)d_in[4];
    const float* b2  = (const float*)d_in[5];
    const float* ws1 = (const float*)d_in[6];
    const float* bs1 = (const float*)d_in[7];
    const float* ws2 = (const float*)d_in[8];
    const float* bs2 = (const float*)d_in[9];
    float* out = (float*)d_out;

    init_counts_kernel<<<1, 32>>>();
    gate_kernel<<<T_TOK / 8, 256>>>(x, gw);
    gemm_kernel<true ><<<dim3(SEG / 128, DFF / 128, N_SEGS), 256>>>(x, w1, ws1, b1, bs1);
    gemm_kernel<false><<<dim3(SEG / 128, DM  / 128, N_SEGS), 256>>>(x, w2, ws2, b2, bs2);
    combine_kernel<<<T_TOK, 256>>>(out);
}

// round 11
// speedup vs baseline: 1.1964x; 1.0914x over previous
#include <cuda_runtime.h>
#include <math.h>

#define T_TOK   8192
#define DM      1024
#define DFF     2048
#define N_EXP   8
#define SEG     8192   // worst-case tokens per expert segment
#define N_SEGS  9      // 8 routed + 1 shared ("expert 8")

// ---------------- scratch (device globals; no runtime allocation) -----------
__device__ int   g_count[N_EXP];
__device__ int   g_slot2tok[N_EXP * SEG];
__device__ int   g_tok_slot[T_TOK * 2];
__device__ float g_tok_w[T_TOK * 2];
__device__ float g_H[(size_t)N_SEGS * SEG * DFF];   // stage-1 activations
__device__ float g_EO[(size_t)N_SEGS * SEG * DM];   // stage-2 per-slot outputs

// ---------------- tf32 helpers ----------------------------------------------
__device__ __forceinline__ unsigned int f2tf(float v) {
    unsigned int r;
    asm("cvt.rna.tf32.f32 %0, %1;" : "=r"(r) : "f"(v));
    return r;
}
// 3xTF32 split: v = hi + lo (both tf32-representable)
__device__ __forceinline__ void split_tf32(float v, unsigned int& hi, unsigned int& lo) {
    hi = f2tf(v);
    lo = f2tf(v - __uint_as_float(hi));
}
// D += A(16x8) * B(8x8), tf32 inputs, fp32 accumulate
__device__ __forceinline__ void mma8(float4& d,
                                     unsigned int a0, unsigned int a1,
                                     unsigned int a2, unsigned int a3,
                                     unsigned int b0, unsigned int b1) {
    asm("mma.sync.aligned.m16n8k8.row.col.f32.tf32.tf32.f32 "
        "{%0,%1,%2,%3}, {%4,%5,%6,%7}, {%8,%9}, {%0,%1,%2,%3};"
        : "+f"(d.x), "+f"(d.y), "+f"(d.z), "+f"(d.w)
        : "r"(a0), "r"(a1), "r"(a2), "r"(a3), "r"(b0), "r"(b1));
}

// ---------------- init ------------------------------------------------------
__global__ void init_counts_kernel() {
    if (threadIdx.x < N_EXP) g_count[threadIdx.x] = 0;
}

// ---------------- gate: 1 warp per token ------------------------------------
__global__ void gate_kernel(const float* __restrict__ x,
                            const float* __restrict__ gw) {
    int warp = (blockIdx.x * blockDim.x + threadIdx.x) >> 5;
    int lane = threadIdx.x & 31;
    if (warp >= T_TOK) return;

    const float4* xr = (const float4*)(x + (size_t)warp * DM);
    float acc[N_EXP];
#pragma unroll
    for (int e = 0; e < N_EXP; e++) acc[e] = 0.f;

    for (int i = lane; i < DM / 4; i += 32) {
        float4 xv = xr[i];
#pragma unroll
        for (int e = 0; e < N_EXP; e++) {
            float4 gv = ((const float4*)(gw + (size_t)e * DM))[i];
            acc[e] += xv.x * gv.x + xv.y * gv.y + xv.z * gv.z + xv.w * gv.w;
        }
    }
#pragma unroll
    for (int e = 0; e < N_EXP; e++) {
#pragma unroll
        for (int off = 16; off > 0; off >>= 1)
            acc[e] += __shfl_xor_sync(0xFFFFFFFFu, acc[e], off);
    }

    if (lane == 0) {
        // top-2 over logits (softmax is monotone); ties -> lowest index (jax top_k)
        int i0 = 0;
#pragma unroll
        for (int e = 1; e < N_EXP; e++) if (acc[e] > acc[i0]) i0 = e;
        int i1 = (i0 == 0) ? 1 : 0;
#pragma unroll
        for (int e = 0; e < N_EXP; e++)
            if (e != i0 && acc[e] > acc[i1]) i1 = e;

        // renormalized top-2 softmax weights: global denominator cancels
        float el = expf(acc[i1] - acc[i0]);
        float w0 = 1.f / (1.f + el);
        float w1 = el / (1.f + el);

        int p0 = atomicAdd(&g_count[i0], 1);
        int p1 = atomicAdd(&g_count[i1], 1);
        int s0 = i0 * SEG + p0;
        int s1 = i1 * SEG + p1;
        g_slot2tok[s0] = warp;
        g_slot2tok[s1] = warp;
        g_tok_slot[warp * 2]     = s0;
        g_tok_slot[warp * 2 + 1] = s1;
        g_tok_w[warp * 2]     = w0;
        g_tok_w[warp * 2 + 1] = w1;
    }
}

// ---------------- grouped NT GEMM (C = A * B^T), 128x128x16, 3xTF32 MMA -----
// Tensor-core path: mma.sync.m16n8k8.tf32 with hi/lo split for fp32 accuracy.
// Software-pipelined: register prefetch of next k-tile + double-buffered smem.
// STAGE1: A = gathered x rows [*,DM], B = w1[e]/ws1 [DFF,DM], C = H, ReLU
// STAGE2: A = H rows          [*,DFF], B = w2[e]/ws2 [DM,DFF], C = EO
template <bool STAGE1>
__global__ __launch_bounds__(256, 1)
void gemm_kernel(const float* __restrict__ X,
                 const float* __restrict__ Wr,
                 const float* __restrict__ Ws,
                 const float* __restrict__ br,
                 const float* __restrict__ bs) {
    constexpr int BM = 128, BN = 128, BK = 16;
    constexpr int SST = 136;               // padded smem stride (8 mod 32 -> conflict-free frags)
    constexpr int N = STAGE1 ? DFF : DM;
    constexpr int K = STAGE1 ? DM  : DFF;

    const int e   = blockIdx.z;
    const int cnt = (e < N_EXP) ? g_count[e] : T_TOK;
    const int m0  = blockIdx.x * BM;
    if (m0 >= cnt) return;
    const int n0 = blockIdx.y * BN;

    const float* Bw   = (e < N_EXP) ? Wr + (size_t)e * N * K : Ws;
    const float* bias = (e < N_EXP) ? br + (size_t)e * N     : bs;

    __shared__ float As[2][BK][SST];
    __shared__ float Bs[2][BK][SST];

    const int tid  = threadIdx.x;
    // loader mapping: each thread owns rows (lRow, lRow+64) x k-quad lKq..lKq+3
    const int lRow = tid & 63;
    const int lKq  = ((tid >> 6) & 3) << 2;   // 0,4,8,12

    const int lane  = tid & 31;
    const int wid   = tid >> 5;
    const int warpM = (wid & 1) * 64;         // 2 warp rows
    const int warpN = (wid >> 1) * 32;        // 4 warp cols
    const int gid   = lane >> 2;              // 0..7
    const int tig   = lane & 3;               // 0..3

    // per-thread A row pointers (rows lRow and lRow+64)
    const float* aP[2];
#pragma unroll
    for (int p = 0; p < 2; p++) {
        int m = m0 + lRow + p * 64;
        if (STAGE1) {
            int tok;
            if (e < N_EXP) tok = (m < cnt) ? g_slot2tok[e * SEG + m] : 0;
            else           tok = m;  // shared expert: identity over all tokens
            aP[p] = X + (size_t)tok * K;
        } else {
            aP[p] = g_H + ((size_t)e * SEG + m) * K;
        }
    }
    const float* bP[2] = { Bw + (size_t)(n0 + lRow) * K,
                           Bw + (size_t)(n0 + lRow + 64) * K };

    // 4x4 grid of m16n8 accumulator fragments
    float4 acc[4][4];
#pragma unroll
    for (int i = 0; i < 4; i++)
#pragma unroll
        for (int j = 0; j < 4; j++) acc[i][j] = make_float4(0.f, 0.f, 0.f, 0.f);

    float4 pva[2], pvb[2];

    // prologue: tile 0
#pragma unroll
    for (int p = 0; p < 2; p++) {
        pva[p] = *(const float4*)(aP[p] + lKq);
        pvb[p] = *(const float4*)(bP[p] + lKq);
    }
#pragma unroll
    for (int p = 0; p < 2; p++) {
        int m = lRow + p * 64;
        As[0][lKq + 0][m] = pva[p].x; As[0][lKq + 1][m] = pva[p].y;
        As[0][lKq + 2][m] = pva[p].z; As[0][lKq + 3][m] = pva[p].w;
        Bs[0][lKq + 0][m] = pvb[p].x; Bs[0][lKq + 1][m] = pvb[p].y;
        Bs[0][lKq + 2][m] = pvb[p].z; Bs[0][lKq + 3][m] = pvb[p].w;
    }
    __syncthreads();

    constexpr int NT = K / BK;
    for (int t = 0; t < NT; t++) {
        // issue next tile's global loads before compute (latency hiding)
        if (t + 1 < NT) {
            int k0 = (t + 1) * BK;
#pragma unroll
            for (int p = 0; p < 2; p++) {
                pva[p] = *(const float4*)(aP[p] + k0 + lKq);
                pvb[p] = *(const float4*)(bP[p] + k0 + lKq);
            }
        }

        const int cur = t & 1;
#pragma unroll
        for (int kb = 0; kb < BK; kb += 8) {
            // B fragments for this k8 (hi/lo split)
            unsigned int bh[4][2], bl[4][2];
#pragma unroll
            for (int nt = 0; nt < 4; nt++) {
                int n = warpN + nt * 8 + gid;
                float b0 = Bs[cur][kb + tig][n];
                float b1 = Bs[cur][kb + tig + 4][n];
                split_tf32(b0, bh[nt][0], bl[nt][0]);
                split_tf32(b1, bh[nt][1], bl[nt][1]);
            }
            // A fragments per 16-row tile, then 3xTF32 mma sweep over nt
#pragma unroll
            for (int mt = 0; mt < 4; mt++) {
                int m = warpM + mt * 16 + gid;
                float a0 = As[cur][kb + tig][m];
                float a1 = As[cur][kb + tig][m + 8];
                float a2 = As[cur][kb + tig + 4][m];
                float a3 = As[cur][kb + tig + 4][m + 8];
                unsigned int ah0, al0, ah1, al1, ah2, al2, ah3, al3;
                split_tf32(a0, ah0, al0);
                split_tf32(a1, ah1, al1);
                split_tf32(a2, ah2, al2);
                split_tf32(a3, ah3, al3);
#pragma unroll
                for (int nt = 0; nt < 4; nt++) {
                    mma8(acc[mt][nt], ah0, ah1, ah2, ah3, bh[nt][0], bh[nt][1]);
                    mma8(acc[mt][nt], ah0, ah1, ah2, ah3, bl[nt][0], bl[nt][1]);
                    mma8(acc[mt][nt], al0, al1, al2, al3, bh[nt][0], bh[nt][1]);
                }
            }
        }

        if (t + 1 < NT) {
            __syncthreads();
            const int nxt = (t + 1) & 1;
#pragma unroll
            for (int p = 0; p < 2; p++) {
                int m = lRow + p * 64;
                As[nxt][lKq + 0][m] = pva[p].x; As[nxt][lKq + 1][m] = pva[p].y;
                As[nxt][lKq + 2][m] = pva[p].z; As[nxt][lKq + 3][m] = pva[p].w;
                Bs[nxt][lKq + 0][m] = pvb[p].x; Bs[nxt][lKq + 1][m] = pvb[p].y;
                Bs[nxt][lKq + 2][m] = pvb[p].z; Bs[nxt][lKq + 3][m] = pvb[p].w;
            }
            __syncthreads();
        }
    }

    // ---------------- epilogue: bias (+ReLU) and store -----------------------
    float* Cbase = STAGE1 ? g_H : g_EO;
    float2 bv[4];
#pragma unroll
    for (int nt = 0; nt < 4; nt++)
        bv[nt] = *(const float2*)(bias + n0 + warpN + nt * 8 + 2 * tig);

#pragma unroll
    for (int mt = 0; mt < 4; mt++) {
#pragma unroll
        for (int h = 0; h < 2; h++) {
            int m = m0 + warpM + mt * 16 + gid + h * 8;
            if (m >= cnt) continue;
            float* crow = Cbase + ((size_t)e * SEG + m) * N + n0 + warpN;
#pragma unroll
            for (int nt = 0; nt < 4; nt++) {
                float2 o;
                if (h == 0) { o.x = acc[mt][nt].x + bv[nt].x; o.y = acc[mt][nt].y + bv[nt].y; }
                else        { o.x = acc[mt][nt].z + bv[nt].x; o.y = acc[mt][nt].w + bv[nt].y; }
                if (STAGE1) { o.x = fmaxf(o.x, 0.f); o.y = fmaxf(o.y, 0.f); }
                *(float2*)(crow + nt * 8 + 2 * tig) = o;
            }
        }
    }
}

// ---------------- combine: weighted routed outputs + shared -----------------
__global__ void combine_kernel(float* __restrict__ out) {
    int t = blockIdx.x;
    int i = threadIdx.x;  // 256 threads, D/4 float4s
    int s0 = g_tok_slot[t * 2];
    int s1 = g_tok_slot[t * 2 + 1];
    float w0 = g_tok_w[t * 2];
    float w1 = g_tok_w[t * 2 + 1];

    const float4* EO = (const float4*)g_EO;
    float4 a = EO[(size_t)s0 * (DM / 4) + i];
    float4 b = EO[(size_t)s1 * (DM / 4) + i];
    float4 c = EO[((size_t)N_EXP * SEG + t) * (DM / 4) + i];
    float4 o;
    o.x = w0 * a.x + w1 * b.x + c.x;
    o.y = w0 * a.y + w1 * b.y + c.y;
    o.z = w0 * a.z + w1 * b.z + c.z;
    o.w = w0 * a.w + w1 * b.w + c.w;
    ((float4*)out)[(size_t)t * (DM / 4) + i] = o;
}

// ---------------- launch -----------------------------------------------------
extern "C" void kernel_launch(void* const* d_in, const int* in_sizes, int n_in,
                              void* d_out, int out_size) {
    const float* x   = (const float*)d_in[0];
    const float* gw  = (const float*)d_in[1];
    const float* w1  = (const float*)d_in[2];
    const float* b1  = (const float*)d_in[3];
    const float* w2  = (const float*)d_in[4];
    const float* b2  = (const float*)d_in[5];
    const float* ws1 = (const float*)d_in[6];
    const float* bs1 = (const float*)d_in[7];
    const float* ws2 = (const float*)d_in[8];
    const float* bs2 = (const float*)d_in[9];
    float* out = (float*)d_out;

    init_counts_kernel<<<1, 32>>>();
    gate_kernel<<<T_TOK / 8, 256>>>(x, gw);
    gemm_kernel<true ><<<dim3(SEG / 128, DFF / 128, N_SEGS), 256>>>(x, w1, ws1, b1, bs1);
    gemm_kernel<false><<<dim3(SEG / 128, DM  / 128, N_SEGS), 256>>>(x, w2, ws2, b2, bs2);
    combine_kernel<<<T_TOK, 256>>>(out);
}

// round 12
// speedup vs baseline: 1.6356x; 1.3671x over previous
#include <cuda_runtime.h>
#include <math.h>

#define T_TOK   8192
#define DM      1024
#define DFF     2048
#define N_EXP   8
#define SEG     8192   // worst-case tokens per expert segment
#define N_SEGS  9      // 8 routed + 1 shared ("expert 8")

// ---------------- scratch (device globals; no runtime allocation) -----------
__device__ int   g_count[N_EXP];
__device__ int   g_slot2tok[N_EXP * SEG];
__device__ int   g_tok_slot[T_TOK * 2];
__device__ float g_tok_w[T_TOK * 2];
__device__ float g_H[(size_t)N_SEGS * SEG * DFF];   // stage-1 activations
__device__ float g_EO[(size_t)N_SEGS * SEG * DM];   // stage-2 per-slot outputs

// ---------------- bf16 split helpers -----------------------------------------
// split (a,b) -> hi packed bf16x2 {lo16=bf(a), hi16=bf(b)} and lo residual pack
__device__ __forceinline__ void split_pair(float a, float b,
                                           unsigned int& hi, unsigned int& lo) {
    asm("cvt.rn.bf16x2.f32 %0, %1, %2;" : "=r"(hi) : "f"(b), "f"(a));
    float ah = __uint_as_float(hi << 16);
    float bh = __uint_as_float(hi & 0xffff0000u);
    asm("cvt.rn.bf16x2.f32 %0, %1, %2;" : "=r"(lo) : "f"(b - bh), "f"(a - ah));
}

__device__ __forceinline__ void ldsm_x4(unsigned int& r0, unsigned int& r1,
                                        unsigned int& r2, unsigned int& r3,
                                        unsigned int addr) {
    asm volatile("ldmatrix.sync.aligned.m8n8.x4.shared.b16 {%0,%1,%2,%3}, [%4];"
                 : "=r"(r0), "=r"(r1), "=r"(r2), "=r"(r3) : "r"(addr));
}
__device__ __forceinline__ void ldsm_x2(unsigned int& r0, unsigned int& r1,
                                        unsigned int addr) {
    asm volatile("ldmatrix.sync.aligned.m8n8.x2.shared.b16 {%0,%1}, [%2];"
                 : "=r"(r0), "=r"(r1) : "r"(addr));
}
// D += A(16x16) * B(16x8), bf16 inputs, fp32 accumulate
__device__ __forceinline__ void mma16(float4& d, const unsigned int* a,
                                      unsigned int b0, unsigned int b1) {
    asm("mma.sync.aligned.m16n8k16.row.col.f32.bf16.bf16.f32 "
        "{%0,%1,%2,%3}, {%4,%5,%6,%7}, {%8,%9}, {%0,%1,%2,%3};"
        : "+f"(d.x), "+f"(d.y), "+f"(d.z), "+f"(d.w)
        : "r"(a[0]), "r"(a[1]), "r"(a[2]), "r"(a[3]), "r"(b0), "r"(b1));
}

// ---------------- init ------------------------------------------------------
__global__ void init_counts_kernel() {
    if (threadIdx.x < N_EXP) g_count[threadIdx.x] = 0;
}

// ---------------- gate: 1 warp per token ------------------------------------
__global__ void gate_kernel(const float* __restrict__ x,
                            const float* __restrict__ gw) {
    int warp = (blockIdx.x * blockDim.x + threadIdx.x) >> 5;
    int lane = threadIdx.x & 31;
    if (warp >= T_TOK) return;

    const float4* xr = (const float4*)(x + (size_t)warp * DM);
    float acc[N_EXP];
#pragma unroll
    for (int e = 0; e < N_EXP; e++) acc[e] = 0.f;

    for (int i = lane; i < DM / 4; i += 32) {
        float4 xv = xr[i];
#pragma unroll
        for (int e = 0; e < N_EXP; e++) {
            float4 gv = ((const float4*)(gw + (size_t)e * DM))[i];
            acc[e] += xv.x * gv.x + xv.y * gv.y + xv.z * gv.z + xv.w * gv.w;
        }
    }
#pragma unroll
    for (int e = 0; e < N_EXP; e++) {
#pragma unroll
        for (int off = 16; off > 0; off >>= 1)
            acc[e] += __shfl_xor_sync(0xFFFFFFFFu, acc[e], off);
    }

    if (lane == 0) {
        // top-2 over logits (softmax is monotone); ties -> lowest index (jax top_k)
        int i0 = 0;
#pragma unroll
        for (int e = 1; e < N_EXP; e++) if (acc[e] > acc[i0]) i0 = e;
        int i1 = (i0 == 0) ? 1 : 0;
#pragma unroll
        for (int e = 0; e < N_EXP; e++)
            if (e != i0 && acc[e] > acc[i1]) i1 = e;

        // renormalized top-2 softmax weights: global denominator cancels
        float el = expf(acc[i1] - acc[i0]);
        float w0 = 1.f / (1.f + el);
        float w1 = el / (1.f + el);

        int p0 = atomicAdd(&g_count[i0], 1);
        int p1 = atomicAdd(&g_count[i1], 1);
        int s0 = i0 * SEG + p0;
        int s1 = i1 * SEG + p1;
        g_slot2tok[s0] = warp;
        g_slot2tok[s1] = warp;
        g_tok_slot[warp * 2]     = s0;
        g_tok_slot[warp * 2 + 1] = s1;
        g_tok_w[warp * 2]     = w0;
        g_tok_w[warp * 2 + 1] = w1;
    }
}

// ---------------- grouped NT GEMM (C = A * B^T), 128x128x16, bf16x2 MMA -----
// fp32 accuracy via 2-way bf16 split (hh + hl + lh), split done loader-side.
// smem tiles: bf16 row-major [row][k16], row stride 48B (ldmatrix conflict-free).
// STAGE1: A = gathered x rows [*,DM], B = w1[e]/ws1 [DFF,DM], C = H, ReLU
// STAGE2: A = H rows          [*,DFF], B = w2[e]/ws2 [DM,DFF], C = EO
template <bool STAGE1>
__global__ __launch_bounds__(256, 1)
void gemm_kernel(const float* __restrict__ X,
                 const float* __restrict__ Wr,
                 const float* __restrict__ Ws,
                 const float* __restrict__ br,
                 const float* __restrict__ bs) {
    constexpr int BM = 128, BN = 128, BK = 16;
    constexpr int RB   = 48;                 // row stride in bytes (16B-aligned, 12-bank step)
    constexpr int TILE = BM * RB;            // 6144 B per tile
    constexpr int N = STAGE1 ? DFF : DM;
    constexpr int K = STAGE1 ? DM  : DFF;

    const int e   = blockIdx.z;
    const int cnt = (e < N_EXP) ? g_count[e] : T_TOK;
    const int m0  = blockIdx.x * BM;
    if (m0 >= cnt) return;
    const int n0 = blockIdx.y * BN;

    const float* Bw   = (e < N_EXP) ? Wr + (size_t)e * N * K : Ws;
    const float* bias = (e < N_EXP) ? br + (size_t)e * N     : bs;

    // [buf][tile: 0=Ah 1=Al 2=Bh 3=Bl]
    __shared__ __align__(16) char sm[2][4][TILE];
    const unsigned int smem_u32 = (unsigned int)__cvta_generic_to_shared(&sm[0][0][0]);

    const int tid  = threadIdx.x;
    const int lRow = tid & 63;
    const int lKq  = ((tid >> 6) & 3) << 2;   // k offset 0,4,8,12 (fp32 elems)

    const int lane  = tid & 31;
    const int wid   = tid >> 5;
    const int warpM = (wid & 1) * 64;         // 2 warp rows
    const int warpN = (wid >> 1) * 32;        // 4 warp cols
    const int gid   = lane >> 2;              // 0..7
    const int tig   = lane & 3;               // 0..3

    // ldmatrix per-lane offsets within a tile
    const unsigned int aOff = (unsigned int)(lane & 15) * RB + ((lane >> 4) & 1) * 16;
    const unsigned int bOff = (unsigned int)(lane & 7)  * RB + ((lane >> 3) & 1) * 16;

    // per-thread A row pointers (rows lRow and lRow+64)
    const float* aP[2];
#pragma unroll
    for (int p = 0; p < 2; p++) {
        int m = m0 + lRow + p * 64;
        if (STAGE1) {
            int tok;
            if (e < N_EXP) tok = (m < cnt) ? g_slot2tok[e * SEG + m] : 0;
            else           tok = m;  // shared expert: identity over all tokens
            aP[p] = X + (size_t)tok * K;
        } else {
            aP[p] = g_H + ((size_t)e * SEG + m) * K;
        }
    }
    const float* bP[2] = { Bw + (size_t)(n0 + lRow) * K,
                           Bw + (size_t)(n0 + lRow + 64) * K };

    // 4x4 grid of m16n8 accumulator fragments
    float4 acc[4][4];
#pragma unroll
    for (int i = 0; i < 4; i++)
#pragma unroll
        for (int j = 0; j < 4; j++) acc[i][j] = make_float4(0.f, 0.f, 0.f, 0.f);

    float4 pva[2], pvb[2];

    // split a float4 and store hi/lo bf16x2 pairs into tiles th/tl at (row,k=lKq)
    auto stage = [&](int buf, int th, float4 v, int row, bool isB) {
        unsigned int h0, l0, h1, l1;
        split_pair(v.x, v.y, h0, l0);
        split_pair(v.z, v.w, h1, l1);
        char* base = &sm[buf][th + (isB ? 2 : 0)][0];
        *(uint2*)(base + row * RB + lKq * 2)        = make_uint2(h0, h1);
        *(uint2*)(base + TILE + row * RB + lKq * 2) = make_uint2(l0, l1);
    };
    // NOTE: tiles Ah/Al and Bh/Bl are adjacent, so "hi tile ptr + TILE" = lo tile.

    // prologue: tile 0
#pragma unroll
    for (int p = 0; p < 2; p++) {
        pva[p] = *(const float4*)(aP[p] + lKq);
        pvb[p] = *(const float4*)(bP[p] + lKq);
    }
#pragma unroll
    for (int p = 0; p < 2; p++) {
        stage(0, 0, pva[p], lRow + p * 64, false);
        stage(0, 0, pvb[p], lRow + p * 64, true);
    }
    __syncthreads();

    constexpr int NT = K / BK;
    for (int t = 0; t < NT; t++) {
        // issue next tile's global loads before compute (latency hiding)
        if (t + 1 < NT) {
            int k0 = (t + 1) * BK;
#pragma unroll
            for (int p = 0; p < 2; p++) {
                pva[p] = *(const float4*)(aP[p] + k0 + lKq);
                pvb[p] = *(const float4*)(bP[p] + k0 + lKq);
            }
        }

        const int cur = t & 1;
        const unsigned int abase = smem_u32 + (cur * 4 + 0) * TILE;
        const unsigned int bbase = smem_u32 + (cur * 4 + 2) * TILE;

        // B fragments (hi & lo) for all 4 n-tiles
        unsigned int bh[4][2], bl[4][2];
#pragma unroll
        for (int nt = 0; nt < 4; nt++) {
            unsigned int off = (unsigned int)(warpN + nt * 8) * RB + bOff;
            ldsm_x2(bh[nt][0], bh[nt][1], bbase + off);
            ldsm_x2(bl[nt][0], bl[nt][1], bbase + TILE + off);
        }
#pragma unroll
        for (int mt = 0; mt < 4; mt++) {
            unsigned int off = (unsigned int)(warpM + mt * 16) * RB + aOff;
            unsigned int ah[4], al[4];
            ldsm_x4(ah[0], ah[1], ah[2], ah[3], abase + off);
            ldsm_x4(al[0], al[1], al[2], al[3], abase + TILE + off);
#pragma unroll
            for (int nt = 0; nt < 4; nt++) {
                mma16(acc[mt][nt], ah, bh[nt][0], bh[nt][1]);
                mma16(acc[mt][nt], ah, bl[nt][0], bl[nt][1]);
                mma16(acc[mt][nt], al, bh[nt][0], bh[nt][1]);
            }
        }

        if (t + 1 < NT) {
            __syncthreads();
            const int nxt = (t + 1) & 1;
#pragma unroll
            for (int p = 0; p < 2; p++) {
                stage(nxt, 0, pva[p], lRow + p * 64, false);
                stage(nxt, 0, pvb[p], lRow + p * 64, true);
            }
            __syncthreads();
        }
    }

    // ---------------- epilogue: bias (+ReLU) and store -----------------------
    float* Cbase = STAGE1 ? g_H : g_EO;
    float2 bv[4];
#pragma unroll
    for (int nt = 0; nt < 4; nt++)
        bv[nt] = *(const float2*)(bias + n0 + warpN + nt * 8 + 2 * tig);

#pragma unroll
    for (int mt = 0; mt < 4; mt++) {
#pragma unroll
        for (int h = 0; h < 2; h++) {
            int m = m0 + warpM + mt * 16 + gid + h * 8;
            if (m >= cnt) continue;
            float* crow = Cbase + ((size_t)e * SEG + m) * N + n0 + warpN;
#pragma unroll
            for (int nt = 0; nt < 4; nt++) {
                float2 o;
                if (h == 0) { o.x = acc[mt][nt].x + bv[nt].x; o.y = acc[mt][nt].y + bv[nt].y; }
                else        { o.x = acc[mt][nt].z + bv[nt].x; o.y = acc[mt][nt].w + bv[nt].y; }
                if (STAGE1) { o.x = fmaxf(o.x, 0.f); o.y = fmaxf(o.y, 0.f); }
                *(float2*)(crow + nt * 8 + 2 * tig) = o;
            }
        }
    }
}

// ---------------- combine: weighted routed outputs + shared -----------------
__global__ void combine_kernel(float* __restrict__ out) {
    int t = blockIdx.x;
    int i = threadIdx.x;  // 256 threads, D/4 float4s
    int s0 = g_tok_slot[t * 2];
    int s1 = g_tok_slot[t * 2 + 1];
    float w0 = g_tok_w[t * 2];
    float w1 = g_tok_w[t * 2 + 1];

    const float4* EO = (const float4*)g_EO;
    float4 a = EO[(size_t)s0 * (DM / 4) + i];
    float4 b = EO[(size_t)s1 * (DM / 4) + i];
    float4 c = EO[((size_t)N_EXP * SEG + t) * (DM / 4) + i];
    float4 o;
    o.x = w0 * a.x + w1 * b.x + c.x;
    o.y = w0 * a.y + w1 * b.y + c.y;
    o.z = w0 * a.z + w1 * b.z + c.z;
    o.w = w0 * a.w + w1 * b.w + c.w;
    ((float4*)out)[(size_t)t * (DM / 4) + i] = o;
}

// ---------------- launch -----------------------------------------------------
extern "C" void kernel_launch(void* const* d_in, const int* in_sizes, int n_in,
                              void* d_out, int out_size) {
    const float* x   = (const float*)d_in[0];
    const float* gw  = (const float*)d_in[1];
    const float* w1  = (const float*)d_in[2];
    const float* b1  = (const float*)d_in[3];
    const float* w2  = (const float*)d_in[4];
    const float* b2  = (const float*)d_in[5];
    const float* ws1 = (const float*)d_in[6];
    const float* bs1 = (const float*)d_in[7];
    const float* ws2 = (const float*)d_in[8];
    const float* bs2 = (const float*)d_in[9];
    float* out = (float*)d_out;

    init_counts_kernel<<<1, 32>>>();
    gate_kernel<<<T_TOK / 8, 256>>>(x, gw);
    gemm_kernel<true ><<<dim3(SEG / 128, DFF / 128, N_SEGS), 256>>>(x, w1, ws1, b1, bs1);
    gemm_kernel<false><<<dim3(SEG / 128, DM  / 128, N_SEGS), 256>>>(x, w2, ws2, b2, bs2);
    combine_kernel<<<T_TOK, 256>>>(out);
}

// round 15
// speedup vs baseline: 2.3371x; 1.4289x over previous
#include <cuda_runtime.h>
#include <cuda_bf16.h>
#include <math.h>

#define T_TOK   8192
#define DM      1024
#define DFF     2048
#define N_EXP   8
#define SEG     8192   // worst-case tokens per expert segment
#define N_SEGS  9      // 8 routed + 1 shared ("expert 8")

// ---------------- scratch (device globals; no runtime allocation) -----------
__device__ int   g_count[N_EXP];
__device__ int   g_slot2tok[N_EXP * SEG];
__device__ int   g_tok_slot[T_TOK * 2];
__device__ float g_tok_w[T_TOK * 2];
__device__ float g_EO[(size_t)N_SEGS * SEG * DM];   // stage-2 per-slot outputs

// pre-split bf16 hi/lo operand buffers (unified: expert 8 = shared expert)
__device__ __nv_bfloat16 g_W1h[(size_t)N_SEGS * DFF * DM];
__device__ __nv_bfloat16 g_W1l[(size_t)N_SEGS * DFF * DM];
__device__ __nv_bfloat16 g_W2h[(size_t)N_SEGS * DM * DFF];
__device__ __nv_bfloat16 g_W2l[(size_t)N_SEGS * DM * DFF];
__device__ __nv_bfloat16 g_Xh[(size_t)T_TOK * DM];
__device__ __nv_bfloat16 g_Xl[(size_t)T_TOK * DM];
__device__ __nv_bfloat16 g_Hh[(size_t)N_SEGS * SEG * DFF];
__device__ __nv_bfloat16 g_Hl[(size_t)N_SEGS * SEG * DFF];
__device__ float g_B1[N_SEGS * DFF];
__device__ float g_B2[N_SEGS * DM];

// ---------------- bf16 split helpers -----------------------------------------
// split (a,b) -> hi packed bf16x2 {lo16=bf(a), hi16=bf(b)} and lo residual pack
__device__ __forceinline__ void split_pair(float a, float b,
                                           unsigned int& hi, unsigned int& lo) {
    asm("cvt.rn.bf16x2.f32 %0, %1, %2;" : "=r"(hi) : "f"(b), "f"(a));
    float ah = __uint_as_float(hi << 16);
    float bh = __uint_as_float(hi & 0xffff0000u);
    asm("cvt.rn.bf16x2.f32 %0, %1, %2;" : "=r"(lo) : "f"(b - bh), "f"(a - ah));
}

__device__ __forceinline__ void ldsm_x4(unsigned int& r0, unsigned int& r1,
                                        unsigned int& r2, unsigned int& r3,
                                        unsigned int addr) {
    asm volatile("ldmatrix.sync.aligned.m8n8.x4.shared.b16 {%0,%1,%2,%3}, [%4];"
                 : "=r"(r0), "=r"(r1), "=r"(r2), "=r"(r3) : "r"(addr));
}
__device__ __forceinline__ void ldsm_x2(unsigned int& r0, unsigned int& r1,
                                        unsigned int addr) {
    asm volatile("ldmatrix.sync.aligned.m8n8.x2.shared.b16 {%0,%1}, [%2];"
                 : "=r"(r0), "=r"(r1) : "r"(addr));
}
// D += A(16x16) * B(16x8), bf16 inputs, fp32 accumulate
__device__ __forceinline__ void mma16(float4& d, const unsigned int* a,
                                      unsigned int b0, unsigned int b1) {
    asm("mma.sync.aligned.m16n8k16.row.col.f32.bf16.bf16.f32 "
        "{%0,%1,%2,%3}, {%4,%5,%6,%7}, {%8,%9}, {%0,%1,%2,%3};"
        : "+f"(d.x), "+f"(d.y), "+f"(d.z), "+f"(d.w)
        : "r"(a[0]), "r"(a[1]), "r"(a[2]), "r"(a[3]), "r"(b0), "r"(b1));
}
__device__ __forceinline__ void cpasync16(unsigned int dst, const void* src) {
    asm volatile("cp.async.cg.shared.global [%0], [%1], 16;"
                 :: "r"(dst), "l"(src) : "memory");
}

// ---------------- init ------------------------------------------------------
__global__ void init_counts_kernel() {
    if (threadIdx.x < N_EXP) g_count[threadIdx.x] = 0;
}

// ---------------- gate: 1 warp per token ------------------------------------
__global__ void gate_kernel(const float* __restrict__ x,
                            const float* __restrict__ gw) {
    int warp = (blockIdx.x * blockDim.x + threadIdx.x) >> 5;
    int lane = threadIdx.x & 31;
    if (warp >= T_TOK) return;

    const float4* xr = (const float4*)(x + (size_t)warp * DM);
    float acc[N_EXP];
#pragma unroll
    for (int e = 0; e < N_EXP; e++) acc[e] = 0.f;

    for (int i = lane; i < DM / 4; i += 32) {
        float4 xv = xr[i];
#pragma unroll
        for (int e = 0; e < N_EXP; e++) {
            float4 gv = ((const float4*)(gw + (size_t)e * DM))[i];
            acc[e] += xv.x * gv.x + xv.y * gv.y + xv.z * gv.z + xv.w * gv.w;
        }
    }
#pragma unroll
    for (int e = 0; e < N_EXP; e++) {
#pragma unroll
        for (int off = 16; off > 0; off >>= 1)
            acc[e] += __shfl_xor_sync(0xFFFFFFFFu, acc[e], off);
    }

    if (lane == 0) {
        int i0 = 0;
#pragma unroll
        for (int e = 1; e < N_EXP; e++) if (acc[e] > acc[i0]) i0 = e;
        int i1 = (i0 == 0) ? 1 : 0;
#pragma unroll
        for (int e = 0; e < N_EXP; e++)
            if (e != i0 && acc[e] > acc[i1]) i1 = e;

        float el = expf(acc[i1] - acc[i0]);
        float w0 = 1.f / (1.f + el);
        float w1 = el / (1.f + el);

        int p0 = atomicAdd(&g_count[i0], 1);
        int p1 = atomicAdd(&g_count[i1], 1);
        int s0 = i0 * SEG + p0;
        int s1 = i1 * SEG + p1;
        g_slot2tok[s0] = warp;
        g_slot2tok[s1] = warp;
        g_tok_slot[warp * 2]     = s0;
        g_tok_slot[warp * 2 + 1] = s1;
        g_tok_w[warp * 2]     = w0;
        g_tok_w[warp * 2 + 1] = w1;
    }
}

// ---------------- pre-split: fp32 -> bf16 hi/lo global buffers ---------------
// WHICH: 0 = W1 (w1 + ws1), 1 = W2 (w2 + ws2), 2 = X
template <int WHICH>
__global__ void split_kernel(const float* __restrict__ srcA,
                             const float* __restrict__ srcB) {
    __nv_bfloat16 *dh, *dl;
    size_t nA4, tot4;
    if (WHICH == 0) {
        dh = g_W1h; dl = g_W1l;
        nA4 = (size_t)N_EXP * DFF * DM / 4; tot4 = (size_t)N_SEGS * DFF * DM / 4;
    } else if (WHICH == 1) {
        dh = g_W2h; dl = g_W2l;
        nA4 = (size_t)N_EXP * DM * DFF / 4; tot4 = (size_t)N_SEGS * DM * DFF / 4;
    } else {
        dh = g_Xh; dl = g_Xl;
        nA4 = (size_t)T_TOK * DM / 4; tot4 = nA4;
    }
    for (size_t i = blockIdx.x * (size_t)blockDim.x + threadIdx.x; i < tot4;
         i += (size_t)gridDim.x * blockDim.x) {
        float4 v = (i < nA4) ? ((const float4*)srcA)[i]
                             : ((const float4*)srcB)[i - nA4];
        unsigned int h0, l0, h1, l1;
        split_pair(v.x, v.y, h0, l0);
        split_pair(v.z, v.w, h1, l1);
        *(uint2*)(dh + i * 4) = make_uint2(h0, h1);
        *(uint2*)(dl + i * 4) = make_uint2(l0, l1);
    }
}

__global__ void bias_kernel(const float* __restrict__ b1,
                            const float* __restrict__ bs1,
                            const float* __restrict__ b2,
                            const float* __restrict__ bs2) {
    int i = blockIdx.x * blockDim.x + threadIdx.x;
    if (i < N_EXP * DFF)        g_B1[i] = b1[i];
    else if (i < N_SEGS * DFF)  g_B1[i] = bs1[i - N_EXP * DFF];
    if (i < N_EXP * DM)         g_B2[i] = b2[i];
    else if (i < N_SEGS * DM)   g_B2[i] = bs2[i - N_EXP * DM];
}

// ---------------- grouped NT GEMM (C = A * B^T), 128x128x16, bf16x2 MMA -----
// Operands pre-split to bf16 hi/lo in global; cp.async.cg double-buffered smem.
// fp32 accuracy via 2-way bf16 split (hh + hl + lh) -- same math as R11.
// STAGE1: A = gathered x (split) -> H (written split bf16), ReLU
// STAGE2: A = H (split)          -> EO fp32
template <bool STAGE1>
__global__ __launch_bounds__(256, 2)
void gemm_kernel() {
    constexpr int BM = 128, BK = 16;
    constexpr int RB   = 48;                 // smem row stride bytes (conflict-free ldmatrix)
    constexpr int TILE = BM * RB;            // 6144 B per tile
    constexpr int N = STAGE1 ? DFF : DM;
    constexpr int K = STAGE1 ? DM  : DFF;

    const int e   = blockIdx.z;
    const int cnt = (e < N_EXP) ? g_count[e] : T_TOK;
    const int m0  = blockIdx.x * BM;
    if (m0 >= cnt) return;
    const int n0 = blockIdx.y * 128;

    const __nv_bfloat16* Wh = (STAGE1 ? g_W1h : g_W2h) + (size_t)e * N * K;
    const __nv_bfloat16* Wl = (STAGE1 ? g_W1l : g_W2l) + (size_t)e * N * K;
    const float* bias = STAGE1 ? (g_B1 + e * DFF) : (g_B2 + e * DM);

    // [buf][tile: 0=Ah 1=Al 2=Bh 3=Bl]
    __shared__ __align__(16) char sm[2][4][TILE];
    const unsigned int smem_u32 = (unsigned int)__cvta_generic_to_shared(&sm[0][0][0]);

    const int tid = threadIdx.x;
    // loader mapping: thread -> (row 0..127, 16B-half 0..1)
    const int lrow  = tid >> 1;
    const int lhalf = tid & 1;
    const unsigned int dstOff = (unsigned int)lrow * RB + lhalf * 16;

    // A source row pointers (bf16, offset by half)
    const __nv_bfloat16 *aH, *aL;
    {
        int m = m0 + lrow;
        if (STAGE1) {
            int tok;
            if (e < N_EXP) tok = (m < cnt) ? g_slot2tok[e * SEG + m] : 0;
            else           tok = m;  // shared expert: identity over all tokens
            aH = g_Xh + (size_t)tok * K + lhalf * 8;
            aL = g_Xl + (size_t)tok * K + lhalf * 8;
        } else {
            aH = g_Hh + ((size_t)e * SEG + m) * K + lhalf * 8;
            aL = g_Hl + ((size_t)e * SEG + m) * K + lhalf * 8;
        }
    }
    const __nv_bfloat16* bH = Wh + (size_t)(n0 + lrow) * K + lhalf * 8;
    const __nv_bfloat16* bL = Wl + (size_t)(n0 + lrow) * K + lhalf * 8;

    const int lane  = tid & 31;
    const int wid   = tid >> 5;
    const int warpM = (wid & 1) * 64;
    const int warpN = (wid >> 1) * 32;
    const int gid   = lane >> 2;
    const int tig   = lane & 3;
    const unsigned int aOff = (unsigned int)(lane & 15) * RB + ((lane >> 4) & 1) * 16;
    const unsigned int bOff = (unsigned int)(lane & 7)  * RB + ((lane >> 3) & 1) * 16;

    float4 acc[4][4];
#pragma unroll
    for (int i = 0; i < 4; i++)
#pragma unroll
        for (int j = 0; j < 4; j++) acc[i][j] = make_float4(0.f, 0.f, 0.f, 0.f);

    auto issue = [&](int t, int buf) {
        int k0 = t * BK;
        unsigned int d = smem_u32 + (unsigned int)buf * 4 * TILE + dstOff;
        cpasync16(d + 0 * TILE, aH + k0);
        cpasync16(d + 1 * TILE, aL + k0);
        cpasync16(d + 2 * TILE, bH + k0);
        cpasync16(d + 3 * TILE, bL + k0);
        asm volatile("cp.async.commit_group;" ::: "memory");
    };

    issue(0, 0);

    constexpr int NT = K / BK;
    for (int t = 0; t < NT; t++) {
        if (t + 1 < NT) {
            issue(t + 1, (t + 1) & 1);
            asm volatile("cp.async.wait_group 1;" ::: "memory");
        } else {
            asm volatile("cp.async.wait_group 0;" ::: "memory");
        }
        __syncthreads();

        const int cur = t & 1;
        const unsigned int abase = smem_u32 + (cur * 4 + 0) * TILE;
        const unsigned int bbase = smem_u32 + (cur * 4 + 2) * TILE;

        unsigned int bh[4][2], bl[4][2];
#pragma unroll
        for (int nt = 0; nt < 4; nt++) {
            unsigned int off = (unsigned int)(warpN + nt * 8) * RB + bOff;
            ldsm_x2(bh[nt][0], bh[nt][1], bbase + off);
            ldsm_x2(bl[nt][0], bl[nt][1], bbase + TILE + off);
        }
#pragma unroll
        for (int mt = 0; mt < 4; mt++) {
            unsigned int off = (unsigned int)(warpM + mt * 16) * RB + aOff;
            unsigned int ah[4], al[4];
            ldsm_x4(ah[0], ah[1], ah[2], ah[3], abase + off);
            ldsm_x4(al[0], al[1], al[2], al[3], abase + TILE + off);
#pragma unroll
            for (int nt = 0; nt < 4; nt++) {
                mma16(acc[mt][nt], ah, bh[nt][0], bh[nt][1]);
                mma16(acc[mt][nt], ah, bl[nt][0], bl[nt][1]);
                mma16(acc[mt][nt], al, bh[nt][0], bh[nt][1]);
            }
        }
        __syncthreads();   // protect buffer before next issue overwrites it
    }

    // ---------------- epilogue: bias (+ReLU) and store -----------------------
    float2 bv[4];
#pragma unroll
    for (int nt = 0; nt < 4; nt++)
        bv[nt] = *(const float2*)(bias + n0 + warpN + nt * 8 + 2 * tig);

#pragma unroll
    for (int mt = 0; mt < 4; mt++) {
#pragma unroll
        for (int h = 0; h < 2; h++) {
            int m = m0 + warpM + mt * 16 + gid + h * 8;
            if (m >= cnt) continue;
            size_t rowbase = ((size_t)e * SEG + m) * N + n0 + warpN;
#pragma unroll
            for (int nt = 0; nt < 4; nt++) {
                float2 o;
                if (h == 0) { o.x = acc[mt][nt].x + bv[nt].x; o.y = acc[mt][nt].y + bv[nt].y; }
                else        { o.x = acc[mt][nt].z + bv[nt].x; o.y = acc[mt][nt].w + bv[nt].y; }
                if (STAGE1) {
                    o.x = fmaxf(o.x, 0.f); o.y = fmaxf(o.y, 0.f);
                    // write H pre-split (hi/lo bf16) for stage-2 consumption
                    unsigned int hh, ll;
                    split_pair(o.x, o.y, hh, ll);
                    size_t idx = rowbase + nt * 8 + 2 * tig;
                    *(unsigned int*)(g_Hh + idx) = hh;
                    *(unsigned int*)(g_Hl + idx) = ll;
                } else {
                    *(float2*)(g_EO + rowbase + nt * 8 + 2 * tig) = o;
                }
            }
        }
    }
}

// ---------------- combine: weighted routed outputs + shared -----------------
__global__ void combine_kernel(float* __restrict__ out) {
    int t = blockIdx.x;
    int i = threadIdx.x;  // 256 threads, D/4 float4s
    int s0 = g_tok_slot[t * 2];
    int s1 = g_tok_slot[t * 2 + 1];
    float w0 = g_tok_w[t * 2];
    float w1 = g_tok_w[t * 2 + 1];

    const float4* EO = (const float4*)g_EO;
    float4 a = EO[(size_t)s0 * (DM / 4) + i];
    float4 b = EO[(size_t)s1 * (DM / 4) + i];
    float4 c = EO[((size_t)N_EXP * SEG + t) * (DM / 4) + i];
    float4 o;
    o.x = w0 * a.x + w1 * b.x + c.x;
    o.y = w0 * a.y + w1 * b.y + c.y;
    o.z = w0 * a.z + w1 * b.z + c.z;
    o.w = w0 * a.w + w1 * b.w + c.w;
    ((float4*)out)[(size_t)t * (DM / 4) + i] = o;
}

// ---------------- launch -----------------------------------------------------
extern "C" void kernel_launch(void* const* d_in, const int* in_sizes, int n_in,
                              void* d_out, int out_size) {
    const float* x   = (const float*)d_in[0];
    const float* gw  = (const float*)d_in[1];
    const float* w1  = (const float*)d_in[2];
    const float* b1  = (const float*)d_in[3];
    const float* w2  = (const float*)d_in[4];
    const float* b2  = (const float*)d_in[5];
    const float* ws1 = (const float*)d_in[6];
    const float* bs1 = (const float*)d_in[7];
    const float* ws2 = (const float*)d_in[8];
    const float* bs2 = (const float*)d_in[9];
    float* out = (float*)d_out;

    init_counts_kernel<<<1, 32>>>();
    gate_kernel<<<T_TOK / 8, 256>>>(x, gw);
    split_kernel<0><<<8192, 256>>>(w1, ws1);
    split_kernel<1><<<8192, 256>>>(w2, ws2);
    split_kernel<2><<<4096, 256>>>(x, x);
    bias_kernel<<<(N_SEGS * DFF + 255) / 256, 256>>>(b1, bs1, b2, bs2);
    gemm_kernel<true ><<<dim3(SEG / 128, DFF / 128, N_SEGS), 256>>>();
    gemm_kernel<false><<<dim3(SEG / 128, DM  / 128, N_SEGS), 256>>>();
    combine_kernel<<<T_TOK, 256>>>(out);
}